// round 1
// baseline (speedup 1.0000x reference)
#include <cuda_runtime.h>
#include <math.h>

// ---------------- Problem constants ----------------
#define BS      8192
#define NL      512
#define ML      32
#define DP      128     // D_PATH
#define G3      384     // 3*D_PATH
#define DR      256     // D_READ
#define NO      3

// GRU kernel tiling
#define BT      28          // samples per chunk
#define NCHUNK  293         // ceil(8192/28)
#define GRU_BLOCKS 148
#define GRU_THREADS 256     // 64 jt x 4 sg, 7 samples per sg-thread

// ---------------- Device scratch (no allocation allowed) ----------------
__device__ float g_flow[BS * DP];                 // 4 MB
__device__ float g_h1[NO * BS * DR];              // 25 MB
__device__ float g_psum[128 * DP];
__device__ float g_psumsq[128 * DP];
__device__ float g_bnA[DP];
__device__ float g_bnB[DP];
__device__ int   g_maxbits;
__device__ int   g_counts[40];
__device__ int   g_offsets[40];
__device__ int   g_order[BS];

// ---------------- small helpers ----------------
__device__ __forceinline__ float seluf(float x) {
    const float sc = 1.0507009873554805f;
    const float al = 1.6732632423543772f;
    return x > 0.f ? sc * x : sc * al * (expf(x) - 1.f);
}
__device__ __forceinline__ float sigm(float x) {
    return 1.f / (1.f + expf(-x));
}

// ---------------- init ----------------
__global__ void k_init() {
    int t = threadIdx.x;
    if (t == 0) g_maxbits = 0;
    if (t < 40) g_counts[t] = 0;
}

// ---------------- global max over link_capacity ----------------
__global__ void k_max(const float* __restrict__ capa) {
    int i = blockIdx.x * blockDim.x + threadIdx.x;
    int stride = gridDim.x * blockDim.x;
    const float4* c4 = (const float4*)capa;
    float m = 0.f;
    for (int q = i; q < (BS * NL) / 4; q += stride) {
        float4 v = c4[q];
        m = fmaxf(m, fmaxf(fmaxf(v.x, v.y), fmaxf(v.z, v.w)));
    }
#pragma unroll
    for (int off = 16; off > 0; off >>= 1)
        m = fmaxf(m, __shfl_down_sync(0xffffffffu, m, off));
    if ((threadIdx.x & 31) == 0) atomicMax(&g_maxbits, __float_as_int(m));
}

// ---------------- hop histogram / scan / scatter (descending hop) ----------------
__global__ void k_hist(const int* __restrict__ hop) {
    int b = blockIdx.x * blockDim.x + threadIdx.x;
    if (b < BS) atomicAdd(&g_counts[hop[b]], 1);
}
__global__ void k_scan() {
    int h = threadIdx.x;
    if (h >= 1 && h <= 32) {
        int off = 0;
        for (int p = h + 1; p <= 32; p++) off += g_counts[p];
        g_offsets[h] = off;
    }
}
__global__ void k_scatter(const int* __restrict__ hop) {
    int b = blockIdx.x * blockDim.x + threadIdx.x;
    if (b < BS) {
        int pos = atomicAdd(&g_offsets[hop[b]], 1);
        g_order[pos] = b;
    }
}

// ---------------- GRU ----------------
// smem: wsh[384*128] swizzled, hsm[28*128], xsm[28*4], sb[28], shop[28], smaxh
__global__ void __launch_bounds__(GRU_THREADS, 1)
k_gru(const float* __restrict__ demand,
      const float* __restrict__ avail,
      const float* __restrict__ capa,
      const float* __restrict__ loss,
      const int*   __restrict__ path,
      const int*   __restrict__ hop,
      const float* __restrict__ w_ih,
      const float* __restrict__ w_hh,
      const float* __restrict__ b_ih,
      const float* __restrict__ b_hh)
{
    extern __shared__ float sm[];
    float* wsh = sm;                       // 49152 floats
    float* hsm = sm + 49152;               // 3584 floats
    float* xsm = hsm + BT * DP;            // 112 floats
    int*   sb   = (int*)(xsm + BT * 4);    // 28
    int*   shop = sb + BT;                 // 28
    int*   smaxh = shop + BT;              // 1

    const int tid = threadIdx.x;
    const int jt = tid & 63;
    const int sg = tid >> 6;

    // Load w_hh into smem with XOR swizzle (conflict-free LDS.128 later)
    const float4* w4g = (const float4*)w_hh;
    for (int q = tid; q < G3 * 32; q += GRU_THREADS) {
        int j = q >> 5, k4 = q & 31;
        float4 v = __ldg(w4g + q);
        ((float4*)wsh)[(j << 5) + (k4 ^ (j & 31))] = v;
    }

    const float maxc = __int_as_float(g_maxbits);
    const float inv_maxc = 1.f / maxc;

    // Per-thread gate constants.  i = dd*3 + g,  j = g*128 + jt + dd*64
    float wih[6][4], bihv[6], bhhv[6];
    int wbase4[6], jx[6];
#pragma unroll
    for (int dd = 0; dd < 2; dd++) {
#pragma unroll
        for (int g = 0; g < 3; g++) {
            int i = dd * 3 + g;
            int j = g * 128 + jt + dd * 64;
#pragma unroll
            for (int c = 0; c < 4; c++) wih[i][c] = __ldg(w_ih + j * 32 + 28 + c);
            bihv[i] = __ldg(b_ih + j);
            bhhv[i] = __ldg(b_hh + j);
            wbase4[i] = j << 5;     // float4 index base
            jx[i] = j & 31;
        }
    }

    for (int cidx = 0; cidx < 2; cidx++) {
        int chunk = (cidx == 0) ? (int)blockIdx.x : (NCHUNK - 1 - (int)blockIdx.x);
        if (cidx == 1 && chunk < GRU_BLOCKS) break;   // LPT pairing; no overlap
        int base = chunk * BT;
        int cnt = min(BT, BS - base);

        if (tid == 0) *smaxh = 0;
        __syncthreads();
        if (tid < BT) {
            int b = -1, hp = 0;
            if (tid < cnt) { b = g_order[base + tid]; hp = hop[b]; }
            sb[tid] = b; shop[tid] = hp;
            atomicMax(smaxh, hp);
        }
        for (int q = tid; q < BT * DP; q += GRU_THREADS) hsm[q] = 0.f;
        __syncthreads();
        if (tid < cnt) hsm[tid * DP + (DP - 1)] = demand[sb[tid]] * inv_maxc;
        __syncthreads();
        int maxh = *smaxh;

        for (int t = 0; t < maxh; t++) {
            // features for this step
            if (tid < BT && t < shop[tid]) {
                int b = sb[tid];
                int l = path[b * ML + t];
                float a = avail[b * NL + l];
                float c = capa[b * NL + l];
                float lo = loss[b * NL + l];
                xsm[tid * 4 + 0] = a * inv_maxc;
                xsm[tid * 4 + 1] = c * inv_maxc;
                xsm[tid * 4 + 2] = a / c;
                xsm[tid * 4 + 3] = lo;
            }
            __syncthreads();

            // gh = h @ w_hh^T for (6 rows x 7 samples) per thread
            float acc[6][7];
#pragma unroll
            for (int i = 0; i < 6; i++)
#pragma unroll
                for (int s = 0; s < 7; s++) acc[i][s] = 0.f;

            const float4* hs4 = (const float4*)hsm;
            const float4* ws4 = (const float4*)wsh;
            const int sbase = sg * 7 * 32;
#pragma unroll 2
            for (int k4 = 0; k4 < 32; k4++) {
                float4 wv[6];
#pragma unroll
                for (int i = 0; i < 6; i++)
                    wv[i] = ws4[wbase4[i] + (k4 ^ jx[i])];
#pragma unroll
                for (int ss = 0; ss < 7; ss++) {
                    float4 hv = hs4[sbase + ss * 32 + k4];
#pragma unroll
                    for (int i = 0; i < 6; i++) {
                        acc[i][ss] += wv[i].x * hv.x;
                        acc[i][ss] += wv[i].y * hv.y;
                        acc[i][ss] += wv[i].z * hv.z;
                        acc[i][ss] += wv[i].w * hv.w;
                    }
                }
            }
            __syncthreads();

            // gates + h update
#pragma unroll
            for (int ss = 0; ss < 7; ss++) {
                int s = sg * 7 + ss;
                int hp = shop[s];
                if (t < hp) {
                    float x0 = xsm[s * 4 + 0], x1 = xsm[s * 4 + 1];
                    float x2 = xsm[s * 4 + 2], x3 = xsm[s * 4 + 3];
#pragma unroll
                    for (int dd = 0; dd < 2; dd++) {
                        int d = jt + dd * 64;
                        int ir = dd * 3 + 0, iz = dd * 3 + 1, in_ = dd * 3 + 2;
                        float gr = bihv[ir] + wih[ir][0] * x0 + wih[ir][1] * x1
                                 + wih[ir][2] * x2 + wih[ir][3] * x3
                                 + acc[ir][ss] + bhhv[ir];
                        float gz = bihv[iz] + wih[iz][0] * x0 + wih[iz][1] * x1
                                 + wih[iz][2] * x2 + wih[iz][3] * x3
                                 + acc[iz][ss] + bhhv[iz];
                        float gni = bihv[in_] + wih[in_][0] * x0 + wih[in_][1] * x1
                                  + wih[in_][2] * x2 + wih[in_][3] * x3;
                        float gnh = acc[in_][ss] + bhhv[in_];
                        float r = sigm(gr);
                        float z = sigm(gz);
                        float n = tanhf(gni + r * gnh);
                        float hold = hsm[s * DP + d];
                        float hnew = (1.f - z) * n + z * hold;
                        hsm[s * DP + d] = hnew;
                        if (t == hp - 1) g_flow[sb[s] * DP + d] = hnew;
                    }
                }
            }
            __syncthreads();
        }
    }
}

// ---------------- BN statistics (deterministic two-pass) ----------------
__global__ void k_bnstats() {
    int d = threadIdx.x;        // 0..127
    int blk = blockIdx.x;       // 0..127
    int r0 = blk * 64;
    float s = 0.f, s2 = 0.f;
    for (int r = 0; r < 64; r++) {
        float v = g_flow[(r0 + r) * DP + d];
        s += v; s2 += v * v;
    }
    g_psum[blk * DP + d] = s;
    g_psumsq[blk * DP + d] = s2;
}
__global__ void k_bnfinal(const float* __restrict__ gamma, const float* __restrict__ beta) {
    int d = threadIdx.x;
    if (d < DP) {
        float s = 0.f, s2 = 0.f;
        for (int blk = 0; blk < 128; blk++) {
            s += g_psum[blk * DP + d];
            s2 += g_psumsq[blk * DP + d];
        }
        float mean = s * (1.f / BS);
        float var = s2 * (1.f / BS) - mean * mean;
        float rstd = rsqrtf(var + 1e-5f);
        float A = rstd * gamma[d];
        g_bnA[d] = A;
        g_bnB[d] = beta[d] - mean * A;
    }
}

// ---------------- GEMM1: h1 = selu(BN(flow) @ rW1[u] + rb1[u]) ----------------
// block tile 64x64, K=128, 256 threads, thread tile 4x4
__global__ void __launch_bounds__(256)
k_g1(const float* __restrict__ rW1, const float* __restrict__ rb1) {
    __shared__ float As[16 * 64];
    __shared__ float Bs[16 * 64];
    int tid = threadIdx.x;
    int m0 = blockIdx.x * 64, n0 = blockIdx.y * 64, u = blockIdx.z;
    int trow = tid >> 4, tcol = tid & 15;
    const float* B = rW1 + u * DP * DR;
    float acc[4][4] = {};

    for (int k0 = 0; k0 < DP; k0 += 16) {
        {   // A tile (BN applied on load)
            int m = tid >> 2, kq = tid & 3;
            float4 v = *(const float4*)(g_flow + (m0 + m) * DP + k0 + kq * 4);
            int kb = kq * 4;
            As[(kb + 0) * 64 + m] = v.x * g_bnA[k0 + kb + 0] + g_bnB[k0 + kb + 0];
            As[(kb + 1) * 64 + m] = v.y * g_bnA[k0 + kb + 1] + g_bnB[k0 + kb + 1];
            As[(kb + 2) * 64 + m] = v.z * g_bnA[k0 + kb + 2] + g_bnB[k0 + kb + 2];
            As[(kb + 3) * 64 + m] = v.w * g_bnA[k0 + kb + 3] + g_bnB[k0 + kb + 3];
        }
        {   // B tile
            int k = tid >> 4, nq = tid & 15;
            *(float4*)&Bs[k * 64 + nq * 4] =
                *(const float4*)(B + (k0 + k) * DR + n0 + nq * 4);
        }
        __syncthreads();
#pragma unroll
        for (int kk = 0; kk < 16; kk++) {
            float4 fa = *(float4*)&As[kk * 64 + trow * 4];
            float4 fb = *(float4*)&Bs[kk * 64 + tcol * 4];
            float av[4] = {fa.x, fa.y, fa.z, fa.w};
            float bv[4] = {fb.x, fb.y, fb.z, fb.w};
#pragma unroll
            for (int i = 0; i < 4; i++)
#pragma unroll
                for (int j = 0; j < 4; j++) acc[i][j] += av[i] * bv[j];
        }
        __syncthreads();
    }
#pragma unroll
    for (int i = 0; i < 4; i++) {
        int row = m0 + trow * 4 + i;
        int n = n0 + tcol * 4;
        float4 o;
        o.x = seluf(acc[i][0] + rb1[u * DR + n + 0]);
        o.y = seluf(acc[i][1] + rb1[u * DR + n + 1]);
        o.z = seluf(acc[i][2] + rb1[u * DR + n + 2]);
        o.w = seluf(acc[i][3] + rb1[u * DR + n + 3]);
        *(float4*)(g_h1 + u * (BS * DR) + row * DR + n) = o;
    }
}

// ---------------- GEMM2: h2 = selu(h1 @ rW2 + rb2); y = h2 . rW3 + rb3 ----------------
// block tile 64x256 (full N so y finishes in-block), 256 threads, thread tile 8x8
__global__ void __launch_bounds__(256)
k_g2(const float* __restrict__ rW2, const float* __restrict__ rb2,
     const float* __restrict__ rW3, const float* __restrict__ rb3,
     float* __restrict__ out) {
    __shared__ float As[16 * 64];
    __shared__ float Bs[16 * 256];
    __shared__ float red[64 * 32];
    int tid = threadIdx.x;
    int m0 = blockIdx.x * 64, u = blockIdx.y;
    int trow = tid >> 5, tcol = tid & 31;
    const float* A = g_h1 + u * (BS * DR);
    const float* B = rW2 + u * DR * DR;
    float w3v[8];
#pragma unroll
    for (int j = 0; j < 8; j++) w3v[j] = __ldg(rW3 + u * DR + tcol * 8 + j);

    float acc[8][8] = {};
    for (int k0 = 0; k0 < DR; k0 += 16) {
        {   // A tile
            int m = tid >> 2, kq = tid & 3;
            float4 v = *(const float4*)(A + (m0 + m) * DR + k0 + kq * 4);
            int kb = kq * 4;
            As[(kb + 0) * 64 + m] = v.x;
            As[(kb + 1) * 64 + m] = v.y;
            As[(kb + 2) * 64 + m] = v.z;
            As[(kb + 3) * 64 + m] = v.w;
        }
#pragma unroll
        for (int r = 0; r < 4; r++) {   // B tile: 16x256
            int idx = r * 256 + tid;
            int k = idx >> 6, nq = idx & 63;
            *(float4*)&Bs[k * 256 + nq * 4] =
                *(const float4*)(B + (k0 + k) * DR + nq * 4);
        }
        __syncthreads();
#pragma unroll
        for (int kk = 0; kk < 16; kk++) {
            float4 a0 = *(float4*)&As[kk * 64 + trow * 8];
            float4 a1 = *(float4*)&As[kk * 64 + trow * 8 + 4];
            float4 b0 = *(float4*)&Bs[kk * 256 + tcol * 8];
            float4 b1 = *(float4*)&Bs[kk * 256 + tcol * 8 + 4];
            float av[8] = {a0.x, a0.y, a0.z, a0.w, a1.x, a1.y, a1.z, a1.w};
            float bv[8] = {b0.x, b0.y, b0.z, b0.w, b1.x, b1.y, b1.z, b1.w};
#pragma unroll
            for (int i = 0; i < 8; i++)
#pragma unroll
                for (int j = 0; j < 8; j++) acc[i][j] += av[i] * bv[j];
        }
        __syncthreads();
    }
#pragma unroll
    for (int i = 0; i < 8; i++) {
        float p = 0.f;
#pragma unroll
        for (int j = 0; j < 8; j++) {
            float h2 = seluf(acc[i][j] + rb2[u * DR + tcol * 8 + j]);
            p += h2 * w3v[j];
        }
        red[(trow * 8 + i) * 32 + tcol] = p;
    }
    __syncthreads();
    if (tid < 64) {
        float y = rb3[u];
#pragma unroll
        for (int c = 0; c < 32; c++) y += red[tid * 32 + c];
        out[(m0 + tid) * NO + u] = y;
    }
}

// ---------------- launcher ----------------
extern "C" void kernel_launch(void* const* d_in, const int* in_sizes, int n_in,
                              void* d_out, int out_size) {
    const float* demand = (const float*)d_in[0];
    const float* avail  = (const float*)d_in[1];
    const float* capa   = (const float*)d_in[2];
    const float* loss   = (const float*)d_in[3];
    const int*   path   = (const int*)d_in[4];
    const int*   hop    = (const int*)d_in[5];
    const float* w_ih   = (const float*)d_in[6];
    const float* w_hh   = (const float*)d_in[7];
    const float* b_ih   = (const float*)d_in[8];
    const float* b_hh   = (const float*)d_in[9];
    const float* gamma  = (const float*)d_in[10];
    const float* beta   = (const float*)d_in[11];
    const float* rW1    = (const float*)d_in[12];
    const float* rb1    = (const float*)d_in[13];
    const float* rW2    = (const float*)d_in[14];
    const float* rb2    = (const float*)d_in[15];
    const float* rW3    = (const float*)d_in[16];
    const float* rb3    = (const float*)d_in[17];
    float* out = (float*)d_out;

    // dynamic smem for GRU: wsh + hsm + xsm + meta
    const int GRU_SMEM = (49152 + BT * DP + BT * 4) * 4 + (2 * BT + 1) * 4 + 256;
    cudaFuncSetAttribute(k_gru, cudaFuncAttributeMaxDynamicSharedMemorySize, GRU_SMEM);

    k_init<<<1, 64>>>();
    k_max<<<256, 256>>>(capa);
    k_hist<<<BS / 256, 256>>>(hop);
    k_scan<<<1, 33>>>();
    k_scatter<<<BS / 256, 256>>>(hop);
    k_gru<<<GRU_BLOCKS, GRU_THREADS, GRU_SMEM>>>(demand, avail, capa, loss, path, hop,
                                                 w_ih, w_hh, b_ih, b_hh);
    k_bnstats<<<128, 128>>>();
    k_bnfinal<<<1, 128>>>(gamma, beta);
    {
        dim3 g1(BS / 64, DR / 64, NO);
        k_g1<<<g1, 256>>>(rW1, rb1);
    }
    {
        dim3 g2(BS / 64, NO);
        k_g2<<<g2, 256>>>(rW2, rb2, rW3, rb3, out);
    }
}